// round 7
// baseline (speedup 1.0000x reference)
#include <cuda_runtime.h>

#define NMAX   100000
#define EMAX   1600000
#define DIN    64
#define NHEAD  4
#define HDIM   16
#define FEAT   64   // NHEAD*HDIM
#define SCAN_B 1024
#define NBMAX  256

// -------- scratch (static device globals; no allocations allowed) ----------
__device__ __align__(16) static float g_h[(size_t)NMAX * FEAT];   // projected node features
__device__ static float g_u[NMAX];
__device__ static float g_v[NMAX];
__device__ __align__(16) static float g_as[NMAX * NHEAD];
__device__ __align__(16) static float g_ad[NMAX * NHEAD];

__device__ static int g_deg[NMAX];
__device__ static int g_cursor[NMAX];      // initialized to offs; scatter bumps it
__device__ static int g_offs[NMAX + 1];
__device__ static int g_srcs[EMAX];        // src node id per edge, sorted by dst
__device__ static int g_bsum[NBMAX];
__device__ static int g_bbase[NBMAX];

struct Params {
    float cu[DIN];   // Wd @ (Wf[0:64]  + Wf[128:192])
    float cv[DIN];   // Wd @ (Wf[64:128] - Wf[128:192])
    float off;       // bd . (wfu + wfv) + bf
    float ba;        // attention bias scalar
};
__device__ static Params g_P;

// ---------------------------------------------------------------------------
// 1) Fold the rank-1 edge linears into per-node projection vectors.
// ---------------------------------------------------------------------------
__global__ void precompute_kernel(const float* __restrict__ Wd,
                                  const float* __restrict__ bd,
                                  const float* __restrict__ Wf,
                                  const float* __restrict__ bf,
                                  const float* __restrict__ ba) {
    __shared__ float wfu[DIN], wfv[DIN], red[DIN];
    int t = threadIdx.x;   // 64 threads
    float f0 = Wf[t], f1 = Wf[DIN + t], f2 = Wf[2 * DIN + t];
    wfu[t] = f0 + f2;
    wfv[t] = f1 - f2;
    __syncthreads();
    float cu = 0.f, cv = 0.f;
#pragma unroll 8
    for (int j = 0; j < DIN; j++) {
        float w = Wd[t * DIN + j];
        cu += w * wfu[j];
        cv += w * wfv[j];
    }
    g_P.cu[t] = cu;
    g_P.cv[t] = cv;
    red[t] = bd[t] * (wfu[t] + wfv[t]);
    __syncthreads();
    if (t == 0) {
        float s = bf[0];
        for (int j = 0; j < DIN; j++) s += red[j];
        g_P.off = s;
        g_P.ba  = ba[0];
    }
}

// ---------------------------------------------------------------------------
// 2) Zero degree array.
// ---------------------------------------------------------------------------
__global__ void zero_deg_kernel(int N) {
    int i = blockIdx.x * blockDim.x + threadIdx.x;
    if (i < N) g_deg[i] = 0;
}

// ---------------------------------------------------------------------------
// 3) Degree histogram over dst.
// ---------------------------------------------------------------------------
__global__ void hist_kernel(const int* __restrict__ dst, int E) {
    int e = blockIdx.x * blockDim.x + threadIdx.x;
    if (e < E) atomicAdd(&g_deg[dst[e]], 1);
}

// ---------------------------------------------------------------------------
// 4a) Per-block partial sums of g_deg.
// ---------------------------------------------------------------------------
__global__ void scan_partial_kernel(int N) {
    __shared__ int sm[SCAN_B];
    int idx = blockIdx.x * SCAN_B + threadIdx.x;
    sm[threadIdx.x] = (idx < N) ? g_deg[idx] : 0;
    __syncthreads();
#pragma unroll
    for (int o = SCAN_B / 2; o > 0; o >>= 1) {
        if (threadIdx.x < o) sm[threadIdx.x] += sm[threadIdx.x + o];
        __syncthreads();
    }
    if (threadIdx.x == 0) g_bsum[blockIdx.x] = sm[0];
}

// ---------------------------------------------------------------------------
// 4b) Exclusive scan of the (<=256) block sums; also write total at offs[N].
// ---------------------------------------------------------------------------
__global__ void scan_base_kernel(int NB, int N) {
    __shared__ int sm[NBMAX];
    int t = threadIdx.x;   // 256 threads
    int v = (t < NB) ? g_bsum[t] : 0;
    sm[t] = v;
    __syncthreads();
#pragma unroll
    for (int o = 1; o < NBMAX; o <<= 1) {
        int tmp = (t >= o) ? sm[t - o] : 0;
        __syncthreads();
        sm[t] += tmp;
        __syncthreads();
    }
    if (t < NB) g_bbase[t] = sm[t] - v;
    if (t == NBMAX - 1) g_offs[N] = sm[NBMAX - 1];
}

// ---------------------------------------------------------------------------
// 4c) Per-block exclusive scan + base; also seeds the scatter cursor.
// ---------------------------------------------------------------------------
__global__ void scan_final_kernel(int N) {
    __shared__ int sm[SCAN_B];
    int idx = blockIdx.x * SCAN_B + threadIdx.x;
    int v = (idx < N) ? g_deg[idx] : 0;
    sm[threadIdx.x] = v;
    __syncthreads();
#pragma unroll
    for (int o = 1; o < SCAN_B; o <<= 1) {
        int tmp = (threadIdx.x >= o) ? sm[threadIdx.x - o] : 0;
        __syncthreads();
        sm[threadIdx.x] += tmp;
        __syncthreads();
    }
    if (idx < N) {
        int off = g_bbase[blockIdx.x] + sm[threadIdx.x] - v;
        g_offs[idx] = off;
        g_cursor[idx] = off;
    }
}

// ---------------------------------------------------------------------------
// 5) Scatter src ids into dst-sorted order (cursor pre-seeded with offsets).
// ---------------------------------------------------------------------------
__global__ void scatter_kernel(const int* __restrict__ src,
                               const int* __restrict__ dst, int E) {
    int e = blockIdx.x * blockDim.x + threadIdx.x;
    if (e >= E) return;
    int pos = atomicAdd(&g_cursor[dst[e]], 1);
    g_srcs[pos] = src[e];
}

// ---------------------------------------------------------------------------
// 6) Per-node projections: h = x@Wl + bl, u = x.cu, v = x.cv,
//    a_s/a_d = per-head dot with Wa halves.
// ---------------------------------------------------------------------------
__global__ void __launch_bounds__(128)
node_kernel(const float* __restrict__ x,
            const float* __restrict__ Wl,
            const float* __restrict__ bl,
            const float* __restrict__ Wa,
            int N) {
    __shared__ float s_wl[DIN * FEAT];
    __shared__ float s_bl[FEAT];
    __shared__ float s_wa[2 * HDIM];
    __shared__ float s_cu[DIN], s_cv[DIN];

    for (int i = threadIdx.x; i < DIN * FEAT; i += blockDim.x) s_wl[i] = Wl[i];
    if (threadIdx.x < FEAT) {
        s_bl[threadIdx.x] = bl[threadIdx.x];
        s_cu[threadIdx.x] = g_P.cu[threadIdx.x];
        s_cv[threadIdx.x] = g_P.cv[threadIdx.x];
    }
    if (threadIdx.x < 2 * HDIM) s_wa[threadIdx.x] = Wa[threadIdx.x];
    __syncthreads();

    int n = blockIdx.x * blockDim.x + threadIdx.x;
    if (n >= N) return;

    float acc[FEAT];
#pragma unroll
    for (int o = 0; o < FEAT; o++) acc[o] = s_bl[o];
    float u = 0.f, v = 0.f;

    const float4* xr = reinterpret_cast<const float4*>(x + (size_t)n * DIN);
#pragma unroll 1
    for (int i4 = 0; i4 < DIN / 4; i4++) {
        float4 xv = xr[i4];
        float xs[4] = {xv.x, xv.y, xv.z, xv.w};
#pragma unroll
        for (int j = 0; j < 4; j++) {
            int i = i4 * 4 + j;
            float xi = xs[j];
            u += xi * s_cu[i];
            v += xi * s_cv[i];
            const float4* wrow = reinterpret_cast<const float4*>(&s_wl[i * FEAT]);
#pragma unroll
            for (int o4 = 0; o4 < FEAT / 4; o4++) {
                float4 wv = wrow[o4];
                acc[o4 * 4 + 0] += xi * wv.x;
                acc[o4 * 4 + 1] += xi * wv.y;
                acc[o4 * 4 + 2] += xi * wv.z;
                acc[o4 * 4 + 3] += xi * wv.w;
            }
        }
    }

    float4* hout = reinterpret_cast<float4*>(&g_h[(size_t)n * FEAT]);
#pragma unroll
    for (int o4 = 0; o4 < FEAT / 4; o4++)
        hout[o4] = make_float4(acc[o4 * 4 + 0], acc[o4 * 4 + 1],
                               acc[o4 * 4 + 2], acc[o4 * 4 + 3]);

    g_u[n] = u;
    g_v[n] = v;

#pragma unroll
    for (int h = 0; h < NHEAD; h++) {
        float as = 0.f, ad = 0.f;
#pragma unroll
        for (int k = 0; k < HDIM; k++) {
            float hv = acc[h * HDIM + k];
            as += hv * s_wa[k];
            ad += hv * s_wa[HDIM + k];
        }
        g_as[n * NHEAD + h] = as;
        g_ad[n * NHEAD + h] = ad;
    }
}

// ---------------------------------------------------------------------------
// 7) CSR reduce: 16 threads per dst node (t*4 = float4 of the 64 output
//    features; head = t>>2). Edge loop unrolled by 2 with independent slots
//    and dual accumulators -> 2x memory-level parallelism per thread.
// ---------------------------------------------------------------------------
__global__ void __launch_bounds__(256)
reduce_kernel(float* __restrict__ out, int N) {
    int gid = blockIdx.x * blockDim.x + threadIdx.x;
    int n = gid >> 4;
    if (n >= N) return;
    int t = gid & 15;
    int head = t >> 2;

    int beg = g_offs[n];
    int end = g_offs[n + 1];

    float vofs = g_v[n] + g_P.off;     // folded per-node sign offset
    float adb  = g_ad[n * NHEAD + head] + g_P.ba;

    float4 acc0 = make_float4(0.f, 0.f, 0.f, 0.f);
    float4 acc1 = make_float4(0.f, 0.f, 0.f, 0.f);
    float dsum0 = 0.f, dsum1 = 0.f;

    int p = beg;
    for (; p + 1 < end; p += 2) {
        int s0 = __ldg(&g_srcs[p]);
        int s1 = __ldg(&g_srcs[p + 1]);
        float  u0  = __ldg(&g_u[s0]);
        float  u1  = __ldg(&g_u[s1]);
        float  a0  = __ldg(&g_as[s0 * NHEAD + head]);
        float  a1  = __ldg(&g_as[s1 * NHEAD + head]);
        float4 h0  = *reinterpret_cast<const float4*>(&g_h[(size_t)s0 * FEAT + t * 4]);
        float4 h1  = *reinterpret_cast<const float4*>(&g_h[(size_t)s1 * FEAT + t * 4]);

        float arg0 = u0 + vofs;
        float sg0 = (arg0 > 0.f) ? 1.f : ((arg0 < 0.f) ? -1.f : 0.f);
        float al0 = sg0 * a0 + adb;
        al0 = (al0 > 0.f) ? al0 : 0.01f * al0;
        float w0 = __expf(al0);
        float ws0 = w0 * sg0;
        acc0.x += ws0 * h0.x; acc0.y += ws0 * h0.y;
        acc0.z += ws0 * h0.z; acc0.w += ws0 * h0.w;
        dsum0 += w0;

        float arg1 = u1 + vofs;
        float sg1 = (arg1 > 0.f) ? 1.f : ((arg1 < 0.f) ? -1.f : 0.f);
        float al1 = sg1 * a1 + adb;
        al1 = (al1 > 0.f) ? al1 : 0.01f * al1;
        float w1 = __expf(al1);
        float ws1 = w1 * sg1;
        acc1.x += ws1 * h1.x; acc1.y += ws1 * h1.y;
        acc1.z += ws1 * h1.z; acc1.w += ws1 * h1.w;
        dsum1 += w1;
    }
    if (p < end) {
        int s0 = __ldg(&g_srcs[p]);
        float  u0 = __ldg(&g_u[s0]);
        float  a0 = __ldg(&g_as[s0 * NHEAD + head]);
        float4 h0 = *reinterpret_cast<const float4*>(&g_h[(size_t)s0 * FEAT + t * 4]);
        float arg0 = u0 + vofs;
        float sg0 = (arg0 > 0.f) ? 1.f : ((arg0 < 0.f) ? -1.f : 0.f);
        float al0 = sg0 * a0 + adb;
        al0 = (al0 > 0.f) ? al0 : 0.01f * al0;
        float w0 = __expf(al0);
        float ws0 = w0 * sg0;
        acc0.x += ws0 * h0.x; acc0.y += ws0 * h0.y;
        acc0.z += ws0 * h0.z; acc0.w += ws0 * h0.w;
        dsum0 += w0;
    }

    float dsum = dsum0 + dsum1;
    float inv = 1.f / fmaxf(dsum, 1e-16f);
    *reinterpret_cast<float4*>(&out[(size_t)n * FEAT + t * 4]) =
        make_float4((acc0.x + acc1.x) * inv, (acc0.y + acc1.y) * inv,
                    (acc0.z + acc1.z) * inv, (acc0.w + acc1.w) * inv);
}

// ---------------------------------------------------------------------------
extern "C" void kernel_launch(void* const* d_in, const int* in_sizes, int n_in,
                              void* d_out, int out_size) {
    const float* x   = (const float*)d_in[0];
    const int*   src = (const int*)  d_in[1];
    const int*   dst = (const int*)  d_in[2];
    const float* Wl  = (const float*)d_in[3];
    const float* bl  = (const float*)d_in[4];
    const float* Wa  = (const float*)d_in[5];
    const float* ba  = (const float*)d_in[6];
    const float* Wd  = (const float*)d_in[7];
    const float* bd  = (const float*)d_in[8];
    const float* Wf  = (const float*)d_in[9];
    const float* bf  = (const float*)d_in[10];
    float* out = (float*)d_out;

    int N = in_sizes[0] / DIN;
    int E = in_sizes[1];
    int NB = (N + SCAN_B - 1) / SCAN_B;

    // One-time stream/event setup (host resources, not device memory).
    static cudaStream_t s_side = nullptr;
    static cudaEvent_t  ev_fork = nullptr, ev_join = nullptr;
    if (s_side == nullptr) {
        cudaStreamCreateWithFlags(&s_side, cudaStreamNonBlocking);
        cudaEventCreateWithFlags(&ev_fork, cudaEventDisableTiming);
        cudaEventCreateWithFlags(&ev_join, cudaEventDisableTiming);
    }

    // Fork: side stream builds the CSR (memory/atomic-bound) while the main
    // stream runs the dense projections (FFMA-bound).
    cudaEventRecord(ev_fork, 0);
    cudaStreamWaitEvent(s_side, ev_fork, 0);

    zero_deg_kernel<<<(N + 255) / 256, 256, 0, s_side>>>(N);
    hist_kernel<<<(E + 255) / 256, 256, 0, s_side>>>(dst, E);
    scan_partial_kernel<<<NB, SCAN_B, 0, s_side>>>(N);
    scan_base_kernel<<<1, NBMAX, 0, s_side>>>(NB, N);
    scan_final_kernel<<<NB, SCAN_B, 0, s_side>>>(N);
    scatter_kernel<<<(E + 255) / 256, 256, 0, s_side>>>(src, dst, E);
    cudaEventRecord(ev_join, s_side);

    precompute_kernel<<<1, 64>>>(Wd, bd, Wf, bf, ba);
    node_kernel<<<(N + 127) / 128, 128>>>(x, Wl, bl, Wa, N);

    // Join, then reduce.
    cudaStreamWaitEvent(0, ev_join, 0);
    long long threads = (long long)N * 16;
    int blocks = (int)((threads + 255) / 256);
    reduce_kernel<<<blocks, 256>>>(out, N);
}

// round 8
// speedup vs baseline: 1.1097x; 1.1097x over previous
#include <cuda_runtime.h>
#include <cuda_fp16.h>

#define NMAX   100000
#define EMAX   1600000
#define DIN    64
#define NHEAD  4
#define HDIM   16
#define FEAT   64   // NHEAD*HDIM
#define SCAN_B 1024
#define NBMAX  256

// -------- scratch (static device globals; no allocations allowed) ----------
__device__ __align__(16) static __half g_h[(size_t)NMAX * FEAT];  // fp16 node features
__device__ static float g_u[NMAX];
__device__ static float g_v[NMAX];
__device__ __align__(16) static float g_as[NMAX * NHEAD];
__device__ __align__(16) static float g_ad[NMAX * NHEAD];

__device__ static int g_deg[NMAX];
__device__ static int g_cursor[NMAX];      // initialized to offs; scatter bumps it
__device__ static int g_offs[NMAX + 1];
__device__ static int g_srcs[EMAX];        // src node id per edge, sorted by dst
__device__ static int g_bsum[NBMAX];
__device__ static int g_bbase[NBMAX];

struct Params {
    float cu[DIN];   // Wd @ (Wf[0:64]  + Wf[128:192])
    float cv[DIN];   // Wd @ (Wf[64:128] - Wf[128:192])
    float off;       // bd . (wfu + wfv) + bf
    float ba;        // attention bias scalar
};
__device__ static Params g_P;

// ---------------------------------------------------------------------------
// 1) Fold the rank-1 edge linears into per-node projection vectors.
// ---------------------------------------------------------------------------
__global__ void precompute_kernel(const float* __restrict__ Wd,
                                  const float* __restrict__ bd,
                                  const float* __restrict__ Wf,
                                  const float* __restrict__ bf,
                                  const float* __restrict__ ba) {
    __shared__ float wfu[DIN], wfv[DIN], red[DIN];
    int t = threadIdx.x;   // 64 threads
    float f0 = Wf[t], f1 = Wf[DIN + t], f2 = Wf[2 * DIN + t];
    wfu[t] = f0 + f2;
    wfv[t] = f1 - f2;
    __syncthreads();
    float cu = 0.f, cv = 0.f;
#pragma unroll 8
    for (int j = 0; j < DIN; j++) {
        float w = Wd[t * DIN + j];
        cu += w * wfu[j];
        cv += w * wfv[j];
    }
    g_P.cu[t] = cu;
    g_P.cv[t] = cv;
    red[t] = bd[t] * (wfu[t] + wfv[t]);
    __syncthreads();
    if (t == 0) {
        float s = bf[0];
        for (int j = 0; j < DIN; j++) s += red[j];
        g_P.off = s;
        g_P.ba  = ba[0];
    }
}

// ---------------------------------------------------------------------------
// 2) Zero degree array.
// ---------------------------------------------------------------------------
__global__ void zero_deg_kernel(int N) {
    int i = blockIdx.x * blockDim.x + threadIdx.x;
    if (i < N) g_deg[i] = 0;
}

// ---------------------------------------------------------------------------
// 3) Degree histogram over dst.
// ---------------------------------------------------------------------------
__global__ void hist_kernel(const int* __restrict__ dst, int E) {
    int e = blockIdx.x * blockDim.x + threadIdx.x;
    if (e < E) atomicAdd(&g_deg[dst[e]], 1);
}

// ---------------------------------------------------------------------------
// 4a) Per-block partial sums of g_deg.
// ---------------------------------------------------------------------------
__global__ void scan_partial_kernel(int N) {
    __shared__ int sm[SCAN_B];
    int idx = blockIdx.x * SCAN_B + threadIdx.x;
    sm[threadIdx.x] = (idx < N) ? g_deg[idx] : 0;
    __syncthreads();
#pragma unroll
    for (int o = SCAN_B / 2; o > 0; o >>= 1) {
        if (threadIdx.x < o) sm[threadIdx.x] += sm[threadIdx.x + o];
        __syncthreads();
    }
    if (threadIdx.x == 0) g_bsum[blockIdx.x] = sm[0];
}

// ---------------------------------------------------------------------------
// 4b) Exclusive scan of the (<=256) block sums; also write total at offs[N].
// ---------------------------------------------------------------------------
__global__ void scan_base_kernel(int NB, int N) {
    __shared__ int sm[NBMAX];
    int t = threadIdx.x;   // 256 threads
    int v = (t < NB) ? g_bsum[t] : 0;
    sm[t] = v;
    __syncthreads();
#pragma unroll
    for (int o = 1; o < NBMAX; o <<= 1) {
        int tmp = (t >= o) ? sm[t - o] : 0;
        __syncthreads();
        sm[t] += tmp;
        __syncthreads();
    }
    if (t < NB) g_bbase[t] = sm[t] - v;
    if (t == NBMAX - 1) g_offs[N] = sm[NBMAX - 1];
}

// ---------------------------------------------------------------------------
// 4c) Per-block exclusive scan + base; also seeds the scatter cursor.
// ---------------------------------------------------------------------------
__global__ void scan_final_kernel(int N) {
    __shared__ int sm[SCAN_B];
    int idx = blockIdx.x * SCAN_B + threadIdx.x;
    int v = (idx < N) ? g_deg[idx] : 0;
    sm[threadIdx.x] = v;
    __syncthreads();
#pragma unroll
    for (int o = 1; o < SCAN_B; o <<= 1) {
        int tmp = (threadIdx.x >= o) ? sm[threadIdx.x - o] : 0;
        __syncthreads();
        sm[threadIdx.x] += tmp;
        __syncthreads();
    }
    if (idx < N) {
        int off = g_bbase[blockIdx.x] + sm[threadIdx.x] - v;
        g_offs[idx] = off;
        g_cursor[idx] = off;
    }
}

// ---------------------------------------------------------------------------
// 5) Scatter src ids into dst-sorted order (cursor pre-seeded with offsets).
// ---------------------------------------------------------------------------
__global__ void scatter_kernel(const int* __restrict__ src,
                               const int* __restrict__ dst, int E) {
    int e = blockIdx.x * blockDim.x + threadIdx.x;
    if (e >= E) return;
    int pos = atomicAdd(&g_cursor[dst[e]], 1);
    g_srcs[pos] = src[e];
}

// ---------------------------------------------------------------------------
// 6) Per-node projections: h = x@Wl + bl (stored fp16), u = x.cu, v = x.cv,
//    a_s/a_d = per-head dot with Wa halves (fp32, from fp32 accumulators).
// ---------------------------------------------------------------------------
__global__ void __launch_bounds__(128)
node_kernel(const float* __restrict__ x,
            const float* __restrict__ Wl,
            const float* __restrict__ bl,
            const float* __restrict__ Wa,
            int N) {
    __shared__ float s_wl[DIN * FEAT];
    __shared__ float s_bl[FEAT];
    __shared__ float s_wa[2 * HDIM];
    __shared__ float s_cu[DIN], s_cv[DIN];

    for (int i = threadIdx.x; i < DIN * FEAT; i += blockDim.x) s_wl[i] = Wl[i];
    if (threadIdx.x < FEAT) {
        s_bl[threadIdx.x] = bl[threadIdx.x];
        s_cu[threadIdx.x] = g_P.cu[threadIdx.x];
        s_cv[threadIdx.x] = g_P.cv[threadIdx.x];
    }
    if (threadIdx.x < 2 * HDIM) s_wa[threadIdx.x] = Wa[threadIdx.x];
    __syncthreads();

    int n = blockIdx.x * blockDim.x + threadIdx.x;
    if (n >= N) return;

    float acc[FEAT];
#pragma unroll
    for (int o = 0; o < FEAT; o++) acc[o] = s_bl[o];
    float u = 0.f, v = 0.f;

    const float4* xr = reinterpret_cast<const float4*>(x + (size_t)n * DIN);
#pragma unroll 1
    for (int i4 = 0; i4 < DIN / 4; i4++) {
        float4 xv = xr[i4];
        float xs[4] = {xv.x, xv.y, xv.z, xv.w};
#pragma unroll
        for (int j = 0; j < 4; j++) {
            int i = i4 * 4 + j;
            float xi = xs[j];
            u += xi * s_cu[i];
            v += xi * s_cv[i];
            const float4* wrow = reinterpret_cast<const float4*>(&s_wl[i * FEAT]);
#pragma unroll
            for (int o4 = 0; o4 < FEAT / 4; o4++) {
                float4 wv = wrow[o4];
                acc[o4 * 4 + 0] += xi * wv.x;
                acc[o4 * 4 + 1] += xi * wv.y;
                acc[o4 * 4 + 2] += xi * wv.z;
                acc[o4 * 4 + 3] += xi * wv.w;
            }
        }
    }

    // Store h as fp16 (halves the reduce-gather traffic).
    __half2* hout = reinterpret_cast<__half2*>(&g_h[(size_t)n * FEAT]);
#pragma unroll
    for (int o2 = 0; o2 < FEAT / 2; o2++)
        hout[o2] = __floats2half2_rn(acc[o2 * 2 + 0], acc[o2 * 2 + 1]);

    g_u[n] = u;
    g_v[n] = v;

#pragma unroll
    for (int h = 0; h < NHEAD; h++) {
        float as = 0.f, ad = 0.f;
#pragma unroll
        for (int k = 0; k < HDIM; k++) {
            float hv = acc[h * HDIM + k];
            as += hv * s_wa[k];
            ad += hv * s_wa[HDIM + k];
        }
        g_as[n * NHEAD + h] = as;
        g_ad[n * NHEAD + h] = ad;
    }
}

// ---------------------------------------------------------------------------
// 7) CSR reduce: 16 threads per dst node (t*4 = 4 consecutive features of the
//    64 outputs; head = t>>2). fp16 h gather (8 B/thread), fp32 accumulation,
//    no atomics, fused normalization; index prefetched one iter ahead (R4
//    structure — the best measured variant).
// ---------------------------------------------------------------------------
__global__ void __launch_bounds__(256)
reduce_kernel(float* __restrict__ out, int N) {
    int gid = blockIdx.x * blockDim.x + threadIdx.x;
    int n = gid >> 4;
    if (n >= N) return;
    int t = gid & 15;
    int head = t >> 2;

    int beg = g_offs[n];
    int end = g_offs[n + 1];

    float vofs = g_v[n] + g_P.off;     // folded per-node sign offset
    float adb  = g_ad[n * NHEAD + head] + g_P.ba;

    float4 acc = make_float4(0.f, 0.f, 0.f, 0.f);
    float dsum = 0.f;

    if (beg < end) {
        int s = __ldg(&g_srcs[beg]);
        for (int p = beg; p < end; p++) {
            int s_next = (p + 1 < end) ? __ldg(&g_srcs[p + 1]) : 0;
            float u  = __ldg(&g_u[s]);
            float as = __ldg(&g_as[s * NHEAD + head]);
            // 4 fp16 features = 8 bytes, loaded as one uint2
            uint2 raw = *reinterpret_cast<const uint2*>(&g_h[(size_t)s * FEAT + t * 4]);
            float2 h01 = __half22float2(*reinterpret_cast<const __half2*>(&raw.x));
            float2 h23 = __half22float2(*reinterpret_cast<const __half2*>(&raw.y));

            float arg = u + vofs;
            float sg = (arg > 0.f) ? 1.f : ((arg < 0.f) ? -1.f : 0.f);
            float al = sg * as + adb;
            al = (al > 0.f) ? al : 0.01f * al;          // leaky_relu
            float w = __expf(al);
            float ws = w * sg;
            acc.x += ws * h01.x;
            acc.y += ws * h01.y;
            acc.z += ws * h23.x;
            acc.w += ws * h23.y;
            dsum += w;
            s = s_next;
        }
    }

    float inv = 1.f / fmaxf(dsum, 1e-16f);
    *reinterpret_cast<float4*>(&out[(size_t)n * FEAT + t * 4]) =
        make_float4(acc.x * inv, acc.y * inv, acc.z * inv, acc.w * inv);
}

// ---------------------------------------------------------------------------
extern "C" void kernel_launch(void* const* d_in, const int* in_sizes, int n_in,
                              void* d_out, int out_size) {
    const float* x   = (const float*)d_in[0];
    const int*   src = (const int*)  d_in[1];
    const int*   dst = (const int*)  d_in[2];
    const float* Wl  = (const float*)d_in[3];
    const float* bl  = (const float*)d_in[4];
    const float* Wa  = (const float*)d_in[5];
    const float* ba  = (const float*)d_in[6];
    const float* Wd  = (const float*)d_in[7];
    const float* bd  = (const float*)d_in[8];
    const float* Wf  = (const float*)d_in[9];
    const float* bf  = (const float*)d_in[10];
    float* out = (float*)d_out;

    int N = in_sizes[0] / DIN;
    int E = in_sizes[1];
    int NB = (N + SCAN_B - 1) / SCAN_B;

    // One-time stream/event setup (host resources, not device memory).
    static cudaStream_t s_side = nullptr;
    static cudaEvent_t  ev_fork = nullptr, ev_join = nullptr;
    if (s_side == nullptr) {
        cudaStreamCreateWithFlags(&s_side, cudaStreamNonBlocking);
        cudaEventCreateWithFlags(&ev_fork, cudaEventDisableTiming);
        cudaEventCreateWithFlags(&ev_join, cudaEventDisableTiming);
    }

    // Fork: side stream builds the CSR (memory/atomic-bound) while the main
    // stream runs the dense projections (FFMA-bound).
    cudaEventRecord(ev_fork, 0);
    cudaStreamWaitEvent(s_side, ev_fork, 0);

    zero_deg_kernel<<<(N + 255) / 256, 256, 0, s_side>>>(N);
    hist_kernel<<<(E + 255) / 256, 256, 0, s_side>>>(dst, E);
    scan_partial_kernel<<<NB, SCAN_B, 0, s_side>>>(N);
    scan_base_kernel<<<1, NBMAX, 0, s_side>>>(NB, N);
    scan_final_kernel<<<NB, SCAN_B, 0, s_side>>>(N);
    scatter_kernel<<<(E + 255) / 256, 256, 0, s_side>>>(src, dst, E);
    cudaEventRecord(ev_join, s_side);

    precompute_kernel<<<1, 64>>>(Wd, bd, Wf, bf, ba);
    node_kernel<<<(N + 127) / 128, 128>>>(x, Wl, bl, Wa, N);

    // Join, then reduce.
    cudaStreamWaitEvent(0, ev_join, 0);
    long long threads = (long long)N * 16;
    int blocks = (int)((threads + 255) / 256);
    reduce_kernel<<<blocks, 256>>>(out, N);
}

// round 9
// speedup vs baseline: 1.1437x; 1.0307x over previous
#include <cuda_runtime.h>
#include <cuda_fp16.h>

#define NMAX   100000
#define EMAX   1600000
#define DIN    64
#define NHEAD  4
#define HDIM   16
#define FEAT   64   // NHEAD*HDIM
#define SCAN_B 1024
#define NBMAX  256

// -------- scratch (static device globals; no allocations allowed) ----------
__device__ __align__(16) static __half g_h[(size_t)NMAX * FEAT];  // fp16 node features
__device__ __align__(16) static float2 g_uas[NMAX * NHEAD];  // (u, as_head) packed, 32B/node
__device__ __align__(16) static float2 g_vad[NMAX * NHEAD];  // (v, ad_head) packed

__device__ static int g_deg[NMAX];
__device__ static int g_cursor[NMAX];      // initialized to offs; scatter bumps it
__device__ static int g_offs[NMAX + 1];
__device__ static int g_srcs[EMAX];        // src node id per edge, sorted by dst
__device__ static int g_bsum[NBMAX];
__device__ static int g_bbase[NBMAX];

struct Params {
    float cu[DIN];   // Wd @ (Wf[0:64]  + Wf[128:192])
    float cv[DIN];   // Wd @ (Wf[64:128] - Wf[128:192])
    float off;       // bd . (wfu + wfv) + bf
    float ba;        // attention bias scalar
};
__device__ static Params g_P;

// ---------------------------------------------------------------------------
// 1) Fold the rank-1 edge linears into per-node projection vectors.
// ---------------------------------------------------------------------------
__global__ void precompute_kernel(const float* __restrict__ Wd,
                                  const float* __restrict__ bd,
                                  const float* __restrict__ Wf,
                                  const float* __restrict__ bf,
                                  const float* __restrict__ ba) {
    __shared__ float wfu[DIN], wfv[DIN], red[DIN];
    int t = threadIdx.x;   // 64 threads
    float f0 = Wf[t], f1 = Wf[DIN + t], f2 = Wf[2 * DIN + t];
    wfu[t] = f0 + f2;
    wfv[t] = f1 - f2;
    __syncthreads();
    float cu = 0.f, cv = 0.f;
#pragma unroll 8
    for (int j = 0; j < DIN; j++) {
        float w = Wd[t * DIN + j];
        cu += w * wfu[j];
        cv += w * wfv[j];
    }
    g_P.cu[t] = cu;
    g_P.cv[t] = cv;
    red[t] = bd[t] * (wfu[t] + wfv[t]);
    __syncthreads();
    if (t == 0) {
        float s = bf[0];
        for (int j = 0; j < DIN; j++) s += red[j];
        g_P.off = s;
        g_P.ba  = ba[0];
    }
}

// ---------------------------------------------------------------------------
// 2) Degree histogram over dst (deg zeroed by cudaMemsetAsync).
// ---------------------------------------------------------------------------
__global__ void hist_kernel(const int* __restrict__ dst, int E) {
    int e = blockIdx.x * blockDim.x + threadIdx.x;
    if (e < E) atomicAdd(&g_deg[dst[e]], 1);
}

// ---------------------------------------------------------------------------
// 3a) Per-block partial sums of g_deg.
// ---------------------------------------------------------------------------
__global__ void scan_partial_kernel(int N) {
    __shared__ int sm[SCAN_B];
    int idx = blockIdx.x * SCAN_B + threadIdx.x;
    sm[threadIdx.x] = (idx < N) ? g_deg[idx] : 0;
    __syncthreads();
#pragma unroll
    for (int o = SCAN_B / 2; o > 0; o >>= 1) {
        if (threadIdx.x < o) sm[threadIdx.x] += sm[threadIdx.x + o];
        __syncthreads();
    }
    if (threadIdx.x == 0) g_bsum[blockIdx.x] = sm[0];
}

// ---------------------------------------------------------------------------
// 3b) Exclusive scan of the (<=256) block sums; also write total at offs[N].
// ---------------------------------------------------------------------------
__global__ void scan_base_kernel(int NB, int N) {
    __shared__ int sm[NBMAX];
    int t = threadIdx.x;   // 256 threads
    int v = (t < NB) ? g_bsum[t] : 0;
    sm[t] = v;
    __syncthreads();
#pragma unroll
    for (int o = 1; o < NBMAX; o <<= 1) {
        int tmp = (t >= o) ? sm[t - o] : 0;
        __syncthreads();
        sm[t] += tmp;
        __syncthreads();
    }
    if (t < NB) g_bbase[t] = sm[t] - v;
    if (t == NBMAX - 1) g_offs[N] = sm[NBMAX - 1];
}

// ---------------------------------------------------------------------------
// 3c) Per-block exclusive scan + base; also seeds the scatter cursor.
// ---------------------------------------------------------------------------
__global__ void scan_final_kernel(int N) {
    __shared__ int sm[SCAN_B];
    int idx = blockIdx.x * SCAN_B + threadIdx.x;
    int v = (idx < N) ? g_deg[idx] : 0;
    sm[threadIdx.x] = v;
    __syncthreads();
#pragma unroll
    for (int o = 1; o < SCAN_B; o <<= 1) {
        int tmp = (threadIdx.x >= o) ? sm[threadIdx.x - o] : 0;
        __syncthreads();
        sm[threadIdx.x] += tmp;
        __syncthreads();
    }
    if (idx < N) {
        int off = g_bbase[blockIdx.x] + sm[threadIdx.x] - v;
        g_offs[idx] = off;
        g_cursor[idx] = off;
    }
}

// ---------------------------------------------------------------------------
// 4) Scatter src ids into dst-sorted order (cursor pre-seeded with offsets).
// ---------------------------------------------------------------------------
__global__ void scatter_kernel(const int* __restrict__ src,
                               const int* __restrict__ dst, int E) {
    int e = blockIdx.x * blockDim.x + threadIdx.x;
    if (e >= E) return;
    int pos = atomicAdd(&g_cursor[dst[e]], 1);
    g_srcs[pos] = src[e];
}

// ---------------------------------------------------------------------------
// 5) Per-node projections: h = x@Wl + bl (stored fp16), packed scalar pairs
//    (u, as_h) and (v, ad_h) per head.
// ---------------------------------------------------------------------------
__global__ void __launch_bounds__(128)
node_kernel(const float* __restrict__ x,
            const float* __restrict__ Wl,
            const float* __restrict__ bl,
            const float* __restrict__ Wa,
            int N) {
    __shared__ float s_wl[DIN * FEAT];
    __shared__ float s_bl[FEAT];
    __shared__ float s_wa[2 * HDIM];
    __shared__ float s_cu[DIN], s_cv[DIN];

    for (int i = threadIdx.x; i < DIN * FEAT; i += blockDim.x) s_wl[i] = Wl[i];
    if (threadIdx.x < FEAT) {
        s_bl[threadIdx.x] = bl[threadIdx.x];
        s_cu[threadIdx.x] = g_P.cu[threadIdx.x];
        s_cv[threadIdx.x] = g_P.cv[threadIdx.x];
    }
    if (threadIdx.x < 2 * HDIM) s_wa[threadIdx.x] = Wa[threadIdx.x];
    __syncthreads();

    int n = blockIdx.x * blockDim.x + threadIdx.x;
    if (n >= N) return;

    float acc[FEAT];
#pragma unroll
    for (int o = 0; o < FEAT; o++) acc[o] = s_bl[o];
    float u = 0.f, v = 0.f;

    const float4* xr = reinterpret_cast<const float4*>(x + (size_t)n * DIN);
#pragma unroll 1
    for (int i4 = 0; i4 < DIN / 4; i4++) {
        float4 xv = xr[i4];
        float xs[4] = {xv.x, xv.y, xv.z, xv.w};
#pragma unroll
        for (int j = 0; j < 4; j++) {
            int i = i4 * 4 + j;
            float xi = xs[j];
            u += xi * s_cu[i];
            v += xi * s_cv[i];
            const float4* wrow = reinterpret_cast<const float4*>(&s_wl[i * FEAT]);
#pragma unroll
            for (int o4 = 0; o4 < FEAT / 4; o4++) {
                float4 wv = wrow[o4];
                acc[o4 * 4 + 0] += xi * wv.x;
                acc[o4 * 4 + 1] += xi * wv.y;
                acc[o4 * 4 + 2] += xi * wv.z;
                acc[o4 * 4 + 3] += xi * wv.w;
            }
        }
    }

    // Store h as fp16 (halves the reduce-gather traffic).
    __half2* hout = reinterpret_cast<__half2*>(&g_h[(size_t)n * FEAT]);
#pragma unroll
    for (int o2 = 0; o2 < FEAT / 2; o2++)
        hout[o2] = __floats2half2_rn(acc[o2 * 2 + 0], acc[o2 * 2 + 1]);

#pragma unroll
    for (int h = 0; h < NHEAD; h++) {
        float as = 0.f, ad = 0.f;
#pragma unroll
        for (int k = 0; k < HDIM; k++) {
            float hv = acc[h * HDIM + k];
            as += hv * s_wa[k];
            ad += hv * s_wa[HDIM + k];
        }
        g_uas[n * NHEAD + h] = make_float2(u, as);
        g_vad[n * NHEAD + h] = make_float2(v, ad);
    }
}

// ---------------------------------------------------------------------------
// 6) CSR reduce: 16 threads per dst node (t*4 = 4 consecutive features of the
//    64 outputs; head = t>>2). Per edge: fp16 h (4 sectors/group) + one
//    packed (u,as) float2 (1 sector/group) + src index. fp32 accumulation,
//    no atomics, fused normalization, index prefetched one iter ahead.
// ---------------------------------------------------------------------------
__global__ void __launch_bounds__(256)
reduce_kernel(float* __restrict__ out, int N) {
    int gid = blockIdx.x * blockDim.x + threadIdx.x;
    int n = gid >> 4;
    if (n >= N) return;
    int t = gid & 15;
    int head = t >> 2;

    int beg = g_offs[n];
    int end = g_offs[n + 1];

    float2 vad = __ldg(&g_vad[n * NHEAD + head]);
    float vofs = vad.x + g_P.off;     // folded per-node sign offset
    float adb  = vad.y + g_P.ba;

    float4 acc = make_float4(0.f, 0.f, 0.f, 0.f);
    float dsum = 0.f;

    if (beg < end) {
        int s = __ldg(&g_srcs[beg]);
        for (int p = beg; p < end; p++) {
            int s_next = (p + 1 < end) ? __ldg(&g_srcs[p + 1]) : 0;
            float2 ua = __ldg(&g_uas[s * NHEAD + head]);
            // 4 fp16 features = 8 bytes, loaded as one uint2
            uint2 raw = *reinterpret_cast<const uint2*>(&g_h[(size_t)s * FEAT + t * 4]);
            float2 h01 = __half22float2(*reinterpret_cast<const __half2*>(&raw.x));
            float2 h23 = __half22float2(*reinterpret_cast<const __half2*>(&raw.y));

            float arg = ua.x + vofs;
            float sg = (arg > 0.f) ? 1.f : ((arg < 0.f) ? -1.f : 0.f);
            float al = sg * ua.y + adb;
            al = (al > 0.f) ? al : 0.01f * al;          // leaky_relu
            float w = __expf(al);
            float ws = w * sg;
            acc.x += ws * h01.x;
            acc.y += ws * h01.y;
            acc.z += ws * h23.x;
            acc.w += ws * h23.y;
            dsum += w;
            s = s_next;
        }
    }

    float inv = 1.f / fmaxf(dsum, 1e-16f);
    *reinterpret_cast<float4*>(&out[(size_t)n * FEAT + t * 4]) =
        make_float4(acc.x * inv, acc.y * inv, acc.z * inv, acc.w * inv);
}

// ---------------------------------------------------------------------------
extern "C" void kernel_launch(void* const* d_in, const int* in_sizes, int n_in,
                              void* d_out, int out_size) {
    const float* x   = (const float*)d_in[0];
    const int*   src = (const int*)  d_in[1];
    const int*   dst = (const int*)  d_in[2];
    const float* Wl  = (const float*)d_in[3];
    const float* bl  = (const float*)d_in[4];
    const float* Wa  = (const float*)d_in[5];
    const float* ba  = (const float*)d_in[6];
    const float* Wd  = (const float*)d_in[7];
    const float* bd  = (const float*)d_in[8];
    const float* Wf  = (const float*)d_in[9];
    const float* bf  = (const float*)d_in[10];
    float* out = (float*)d_out;

    int N = in_sizes[0] / DIN;
    int E = in_sizes[1];
    int NB = (N + SCAN_B - 1) / SCAN_B;

    // One-time stream/event setup (host resources, not device memory).
    static cudaStream_t s_side = nullptr;
    static cudaEvent_t  ev_fork = nullptr, ev_join = nullptr;
    static int* p_deg = nullptr;
    if (s_side == nullptr) {
        cudaStreamCreateWithFlags(&s_side, cudaStreamNonBlocking);
        cudaEventCreateWithFlags(&ev_fork, cudaEventDisableTiming);
        cudaEventCreateWithFlags(&ev_join, cudaEventDisableTiming);
        cudaGetSymbolAddress((void**)&p_deg, g_deg);
    }

    // Fork: side stream builds the CSR (memory/atomic-bound) while the main
    // stream runs the dense projections (FFMA-bound).
    cudaEventRecord(ev_fork, 0);
    cudaStreamWaitEvent(s_side, ev_fork, 0);

    cudaMemsetAsync(p_deg, 0, (size_t)N * sizeof(int), s_side);
    hist_kernel<<<(E + 255) / 256, 256, 0, s_side>>>(dst, E);
    scan_partial_kernel<<<NB, SCAN_B, 0, s_side>>>(N);
    scan_base_kernel<<<1, NBMAX, 0, s_side>>>(NB, N);
    scan_final_kernel<<<NB, SCAN_B, 0, s_side>>>(N);
    scatter_kernel<<<(E + 255) / 256, 256, 0, s_side>>>(src, dst, E);
    cudaEventRecord(ev_join, s_side);

    precompute_kernel<<<1, 64>>>(Wd, bd, Wf, bf, ba);
    node_kernel<<<(N + 127) / 128, 128>>>(x, Wl, bl, Wa, N);

    // Join, then reduce.
    cudaStreamWaitEvent(0, ev_join, 0);
    long long threads = (long long)N * 16;
    int blocks = (int)((threads + 255) / 256);
    reduce_kernel<<<blocks, 256>>>(out, N);
}

// round 10
// speedup vs baseline: 1.1500x; 1.0054x over previous
#include <cuda_runtime.h>
#include <cuda_fp16.h>

#define NMAX   100000
#define EMAX   1600000
#define DIN    64
#define NHEAD  4
#define HDIM   16
#define FEAT   64   // NHEAD*HDIM
#define SCAN_B 1024
#define NBMAX  256

// -------- scratch (static device globals; no allocations allowed) ----------
__device__ __align__(16) static __half g_h[(size_t)NMAX * FEAT];  // fp16 node features
__device__ __align__(16) static float2 g_uas[NMAX * NHEAD];  // (u, as_head) packed
__device__ __align__(16) static float2 g_vad[NMAX * NHEAD];  // (v, ad_head) packed

// deg + publish-flags share one memset region: [0,NMAX) = deg, [NMAX,NMAX+NBMAX) = flags
__device__ static int g_degfv[NMAX + NBMAX];
__device__ static int g_cursor[NMAX];      // seeded with offs; scatter bumps it
__device__ static int g_offs[NMAX + 1];
__device__ static int g_srcs[EMAX];        // src node id per edge, sorted by dst

struct Params {
    float cu[DIN];   // Wd @ (Wf[0:64]  + Wf[128:192])
    float cv[DIN];   // Wd @ (Wf[64:128] - Wf[128:192])
    float off;       // bd . (wfu + wfv) + bf
    float ba;        // attention bias scalar
};
__device__ static Params g_P;

// ---------------------------------------------------------------------------
// 1) Fold the rank-1 edge linears into per-node projection vectors.
// ---------------------------------------------------------------------------
__global__ void precompute_kernel(const float* __restrict__ Wd,
                                  const float* __restrict__ bd,
                                  const float* __restrict__ Wf,
                                  const float* __restrict__ bf,
                                  const float* __restrict__ ba) {
    __shared__ float wfu[DIN], wfv[DIN], red[DIN];
    int t = threadIdx.x;   // 64 threads
    float f0 = Wf[t], f1 = Wf[DIN + t], f2 = Wf[2 * DIN + t];
    wfu[t] = f0 + f2;
    wfv[t] = f1 - f2;
    __syncthreads();
    float cu = 0.f, cv = 0.f;
#pragma unroll 8
    for (int j = 0; j < DIN; j++) {
        float w = Wd[t * DIN + j];
        cu += w * wfu[j];
        cv += w * wfv[j];
    }
    g_P.cu[t] = cu;
    g_P.cv[t] = cv;
    red[t] = bd[t] * (wfu[t] + wfv[t]);
    __syncthreads();
    if (t == 0) {
        float s = bf[0];
        for (int j = 0; j < DIN; j++) s += red[j];
        g_P.off = s;
        g_P.ba  = ba[0];
    }
}

// ---------------------------------------------------------------------------
// 2) Degree histogram over dst (deg zeroed by cudaMemsetAsync).
// ---------------------------------------------------------------------------
__global__ void hist_kernel(const int* __restrict__ dst, int E) {
    int e = blockIdx.x * blockDim.x + threadIdx.x;
    if (e < E) atomicAdd(&g_degfv[dst[e]], 1);
}

// ---------------------------------------------------------------------------
// 3) Single-pass exclusive scan (98 co-resident blocks, aggregate lookback).
//    Each block: local scan -> publish aggregate+1 into flag slot ->
//    poll predecessors' aggregates -> base -> write offs + cursor.
// ---------------------------------------------------------------------------
__global__ void scan_onepass_kernel(int N, int NB) {
    __shared__ int sm[SCAN_B];
    __shared__ int s_base;
    int b = blockIdx.x;
    int tid = threadIdx.x;
    int idx = b * SCAN_B + tid;

    int v = (idx < N) ? g_degfv[idx] : 0;
    sm[tid] = v;
    __syncthreads();
#pragma unroll
    for (int o = 1; o < SCAN_B; o <<= 1) {
        int tmp = (tid >= o) ? sm[tid - o] : 0;
        __syncthreads();
        sm[tid] += tmp;
        __syncthreads();
    }
    int incl = sm[tid];
    int agg = sm[SCAN_B - 1];

    // Publish this block's aggregate (flag = agg+1, slot zeroed by memset).
    if (tid == 0) {
        __threadfence();
        atomicExch(&g_degfv[NMAX + b], agg + 1);
    }

    // Warp 0 gathers predecessor aggregates (b <= 97 so <=4 per lane).
    if (tid < 32) {
        int contrib = 0;
        for (int t = tid; t < b; t += 32) {
            int fv;
            do { fv = atomicAdd(&g_degfv[NMAX + t], 0); } while (fv == 0);
            contrib += fv - 1;
        }
#pragma unroll
        for (int o = 16; o > 0; o >>= 1)
            contrib += __shfl_down_sync(0xffffffffu, contrib, o);
        if (tid == 0) s_base = contrib;
    }
    __syncthreads();
    int base = s_base;

    if (idx < N) {
        int off = base + incl - v;
        g_offs[idx] = off;
        g_cursor[idx] = off;
    }
    if (b == NB - 1 && tid == 0) g_offs[N] = base + agg;
}

// ---------------------------------------------------------------------------
// 4) Scatter src ids into dst-sorted order (cursor pre-seeded with offsets).
// ---------------------------------------------------------------------------
__global__ void scatter_kernel(const int* __restrict__ src,
                               const int* __restrict__ dst, int E) {
    int e = blockIdx.x * blockDim.x + threadIdx.x;
    if (e >= E) return;
    int pos = atomicAdd(&g_cursor[dst[e]], 1);
    g_srcs[pos] = src[e];
}

// ---------------------------------------------------------------------------
// 5) Per-node projections with packed fp32x2 FMA (Blackwell FFMA2):
//    h = x@Wl + bl (stored fp16), packed (u, as_h) and (v, ad_h) per head.
// ---------------------------------------------------------------------------
__global__ void __launch_bounds__(128)
node_kernel(const float* __restrict__ x,
            const float* __restrict__ Wl,
            const float* __restrict__ bl,
            const float* __restrict__ Wa,
            int N) {
    __shared__ __align__(16) float s_wl[DIN * FEAT];
    __shared__ __align__(16) float s_bl[FEAT];
    __shared__ float s_wa[2 * HDIM];
    __shared__ float s_cu[DIN], s_cv[DIN];

    for (int i = threadIdx.x; i < DIN * FEAT; i += blockDim.x) s_wl[i] = Wl[i];
    if (threadIdx.x < FEAT) {
        s_bl[threadIdx.x] = bl[threadIdx.x];
        s_cu[threadIdx.x] = g_P.cu[threadIdx.x];
        s_cv[threadIdx.x] = g_P.cv[threadIdx.x];
    }
    if (threadIdx.x < 2 * HDIM) s_wa[threadIdx.x] = Wa[threadIdx.x];
    __syncthreads();

    int n = blockIdx.x * blockDim.x + threadIdx.x;
    if (n >= N) return;

    // 32 packed f32x2 accumulators (= 64 floats), seeded with bias.
    unsigned long long acc2[FEAT / 2];
    const ulonglong2* blp = reinterpret_cast<const ulonglong2*>(s_bl);
#pragma unroll
    for (int q = 0; q < FEAT / 4; q++) {
        ulonglong2 b2 = blp[q];
        acc2[q * 2 + 0] = b2.x;
        acc2[q * 2 + 1] = b2.y;
    }
    float u = 0.f, v = 0.f;

    const float4* xr = reinterpret_cast<const float4*>(x + (size_t)n * DIN);
#pragma unroll 1
    for (int i4 = 0; i4 < DIN / 4; i4++) {
        float4 xv = xr[i4];
        float xs[4] = {xv.x, xv.y, xv.z, xv.w};
#pragma unroll
        for (int j = 0; j < 4; j++) {
            int i = i4 * 4 + j;
            float xi = xs[j];
            u += xi * s_cu[i];
            v += xi * s_cv[i];
            unsigned long long xi2;
            asm("mov.b64 %0, {%1, %1};" : "=l"(xi2) : "f"(xi));
            const ulonglong2* wrow =
                reinterpret_cast<const ulonglong2*>(&s_wl[i * FEAT]);
#pragma unroll
            for (int q = 0; q < FEAT / 4; q++) {
                ulonglong2 wv = wrow[q];
                asm("fma.rn.f32x2 %0, %1, %2, %0;"
                    : "+l"(acc2[q * 2 + 0]) : "l"(wv.x), "l"(xi2));
                asm("fma.rn.f32x2 %0, %1, %2, %0;"
                    : "+l"(acc2[q * 2 + 1]) : "l"(wv.y), "l"(xi2));
            }
        }
    }

    // Unpack to scalars for fp16 store + head dot products.
    float accf[FEAT];
#pragma unroll
    for (int k = 0; k < FEAT / 2; k++)
        asm("mov.b64 {%0, %1}, %2;"
            : "=f"(accf[2 * k]), "=f"(accf[2 * k + 1]) : "l"(acc2[k]));

    __half2* hout = reinterpret_cast<__half2*>(&g_h[(size_t)n * FEAT]);
#pragma unroll
    for (int o2 = 0; o2 < FEAT / 2; o2++)
        hout[o2] = __floats2half2_rn(accf[o2 * 2 + 0], accf[o2 * 2 + 1]);

#pragma unroll
    for (int h = 0; h < NHEAD; h++) {
        float as = 0.f, ad = 0.f;
#pragma unroll
        for (int k = 0; k < HDIM; k++) {
            float hv = accf[h * HDIM + k];
            as += hv * s_wa[k];
            ad += hv * s_wa[HDIM + k];
        }
        g_uas[n * NHEAD + h] = make_float2(u, as);
        g_vad[n * NHEAD + h] = make_float2(v, ad);
    }
}

// ---------------------------------------------------------------------------
// 6) CSR reduce: 16 threads per dst node (t*4 = 4 consecutive features of the
//    64 outputs; head = t>>2). fp16 h gather + packed (u,as) float2.
//    fp32 accumulation, no atomics, fused normalization, index prefetch.
// ---------------------------------------------------------------------------
__global__ void __launch_bounds__(256)
reduce_kernel(float* __restrict__ out, int N) {
    int gid = blockIdx.x * blockDim.x + threadIdx.x;
    int n = gid >> 4;
    if (n >= N) return;
    int t = gid & 15;
    int head = t >> 2;

    int beg = g_offs[n];
    int end = g_offs[n + 1];

    float2 vad = __ldg(&g_vad[n * NHEAD + head]);
    float vofs = vad.x + g_P.off;     // folded per-node sign offset
    float adb  = vad.y + g_P.ba;

    float4 acc = make_float4(0.f, 0.f, 0.f, 0.f);
    float dsum = 0.f;

    if (beg < end) {
        int s = __ldg(&g_srcs[beg]);
        for (int p = beg; p < end; p++) {
            int s_next = (p + 1 < end) ? __ldg(&g_srcs[p + 1]) : 0;
            float2 ua = __ldg(&g_uas[s * NHEAD + head]);
            uint2 raw = *reinterpret_cast<const uint2*>(&g_h[(size_t)s * FEAT + t * 4]);
            float2 h01 = __half22float2(*reinterpret_cast<const __half2*>(&raw.x));
            float2 h23 = __half22float2(*reinterpret_cast<const __half2*>(&raw.y));

            float arg = ua.x + vofs;
            float sg = (arg > 0.f) ? 1.f : ((arg < 0.f) ? -1.f : 0.f);
            float al = sg * ua.y + adb;
            al = (al > 0.f) ? al : 0.01f * al;          // leaky_relu
            float w = __expf(al);
            float ws = w * sg;
            acc.x += ws * h01.x;
            acc.y += ws * h01.y;
            acc.z += ws * h23.x;
            acc.w += ws * h23.y;
            dsum += w;
            s = s_next;
        }
    }

    float inv = 1.f / fmaxf(dsum, 1e-16f);
    *reinterpret_cast<float4*>(&out[(size_t)n * FEAT + t * 4]) =
        make_float4(acc.x * inv, acc.y * inv, acc.z * inv, acc.w * inv);
}

// ---------------------------------------------------------------------------
extern "C" void kernel_launch(void* const* d_in, const int* in_sizes, int n_in,
                              void* d_out, int out_size) {
    const float* x   = (const float*)d_in[0];
    const int*   src = (const int*)  d_in[1];
    const int*   dst = (const int*)  d_in[2];
    const float* Wl  = (const float*)d_in[3];
    const float* bl  = (const float*)d_in[4];
    const float* Wa  = (const float*)d_in[5];
    const float* ba  = (const float*)d_in[6];
    const float* Wd  = (const float*)d_in[7];
    const float* bd  = (const float*)d_in[8];
    const float* Wf  = (const float*)d_in[9];
    const float* bf  = (const float*)d_in[10];
    float* out = (float*)d_out;

    int N = in_sizes[0] / DIN;
    int E = in_sizes[1];
    int NB = (N + SCAN_B - 1) / SCAN_B;

    // One-time stream/event setup (host resources, not device memory).
    static cudaStream_t s_side = nullptr;
    static cudaEvent_t  ev_fork = nullptr, ev_join = nullptr;
    static int* p_degfv = nullptr;
    if (s_side == nullptr) {
        cudaStreamCreateWithFlags(&s_side, cudaStreamNonBlocking);
        cudaEventCreateWithFlags(&ev_fork, cudaEventDisableTiming);
        cudaEventCreateWithFlags(&ev_join, cudaEventDisableTiming);
        cudaGetSymbolAddress((void**)&p_degfv, g_degfv);
    }

    // Fork: side stream builds the CSR (memory/atomic-bound) while the main
    // stream runs the dense projections (FFMA-bound).
    cudaEventRecord(ev_fork, 0);
    cudaStreamWaitEvent(s_side, ev_fork, 0);

    // Zero deg + publish-flag slots in one memset.
    cudaMemsetAsync(p_degfv, 0, (size_t)(N + NB) * sizeof(int), s_side);
    hist_kernel<<<(E + 255) / 256, 256, 0, s_side>>>(dst, E);
    scan_onepass_kernel<<<NB, SCAN_B, 0, s_side>>>(N, NB);
    scatter_kernel<<<(E + 255) / 256, 256, 0, s_side>>>(src, dst, E);
    cudaEventRecord(ev_join, s_side);

    precompute_kernel<<<1, 64>>>(Wd, bd, Wf, bf, ba);
    node_kernel<<<(N + 127) / 128, 128>>>(x, Wl, bl, Wa, N);

    // Join, then reduce.
    cudaStreamWaitEvent(0, ev_join, 0);
    long long threads = (long long)N * 16;
    int blocks = (int)((threads + 255) / 256);
    reduce_kernel<<<blocks, 256>>>(out, N);
}

// round 11
// speedup vs baseline: 1.2866x; 1.1188x over previous
#include <cuda_runtime.h>
#include <cuda_fp16.h>

#define NMAX   100000
#define EMAX   1600000
#define DIN    64
#define NHEAD  4
#define HDIM   16
#define FEAT   64   // NHEAD*HDIM
#define SCAN_B 1024
#define NBMAX  256

// -------- scratch (static device globals; no allocations allowed) ----------
__device__ __align__(16) static __half g_h[(size_t)NMAX * FEAT];  // fp16 node features
__device__ __align__(16) static float2 g_uas[NMAX * NHEAD];  // (u, as_head) packed
__device__ __align__(16) static float2 g_vad[NMAX * NHEAD];  // (v, ad_head) packed

// deg + publish-flags share one memset region: [0,NMAX) = deg, [NMAX,NMAX+NBMAX) = flags
__device__ static int g_degfv[NMAX + NBMAX];
__device__ static int g_cursor[NMAX];      // seeded with offs; scatter bumps it
__device__ static int g_offs[NMAX + 1];
__device__ static int g_srcs[EMAX];        // src node id per edge, sorted by dst

struct Params {
    float cu[DIN];   // Wd @ (Wf[0:64]  + Wf[128:192])
    float cv[DIN];   // Wd @ (Wf[64:128] - Wf[128:192])
    float off;       // bd . (wfu + wfv) + bf
    float ba;        // attention bias scalar
};
__device__ static Params g_P;

// ---------------------------------------------------------------------------
// 1) Fold the rank-1 edge linears into per-node projection vectors.
// ---------------------------------------------------------------------------
__global__ void precompute_kernel(const float* __restrict__ Wd,
                                  const float* __restrict__ bd,
                                  const float* __restrict__ Wf,
                                  const float* __restrict__ bf,
                                  const float* __restrict__ ba) {
    __shared__ float wfu[DIN], wfv[DIN], red[DIN];
    int t = threadIdx.x;   // 64 threads
    float f0 = Wf[t], f1 = Wf[DIN + t], f2 = Wf[2 * DIN + t];
    wfu[t] = f0 + f2;
    wfv[t] = f1 - f2;
    __syncthreads();
    float cu = 0.f, cv = 0.f;
#pragma unroll 8
    for (int j = 0; j < DIN; j++) {
        float w = Wd[t * DIN + j];
        cu += w * wfu[j];
        cv += w * wfv[j];
    }
    g_P.cu[t] = cu;
    g_P.cv[t] = cv;
    red[t] = bd[t] * (wfu[t] + wfv[t]);
    __syncthreads();
    if (t == 0) {
        float s = bf[0];
        for (int j = 0; j < DIN; j++) s += red[j];
        g_P.off = s;
        g_P.ba  = ba[0];
    }
}

// ---------------------------------------------------------------------------
// 2) Degree histogram over dst (deg zeroed by cudaMemsetAsync).
// ---------------------------------------------------------------------------
__global__ void hist_kernel(const int* __restrict__ dst, int E) {
    int e = blockIdx.x * blockDim.x + threadIdx.x;
    if (e < E) atomicAdd(&g_degfv[dst[e]], 1);
}

// ---------------------------------------------------------------------------
// 3) Single-pass exclusive scan (98 co-resident blocks, aggregate lookback).
// ---------------------------------------------------------------------------
__global__ void scan_onepass_kernel(int N, int NB) {
    __shared__ int sm[SCAN_B];
    __shared__ int s_base;
    int b = blockIdx.x;
    int tid = threadIdx.x;
    int idx = b * SCAN_B + tid;

    int v = (idx < N) ? g_degfv[idx] : 0;
    sm[tid] = v;
    __syncthreads();
#pragma unroll
    for (int o = 1; o < SCAN_B; o <<= 1) {
        int tmp = (tid >= o) ? sm[tid - o] : 0;
        __syncthreads();
        sm[tid] += tmp;
        __syncthreads();
    }
    int incl = sm[tid];
    int agg = sm[SCAN_B - 1];

    if (tid == 0) {
        __threadfence();
        atomicExch(&g_degfv[NMAX + b], agg + 1);
    }

    if (tid < 32) {
        int contrib = 0;
        for (int t = tid; t < b; t += 32) {
            int fv;
            do { fv = atomicAdd(&g_degfv[NMAX + t], 0); } while (fv == 0);
            contrib += fv - 1;
        }
#pragma unroll
        for (int o = 16; o > 0; o >>= 1)
            contrib += __shfl_down_sync(0xffffffffu, contrib, o);
        if (tid == 0) s_base = contrib;
    }
    __syncthreads();
    int base = s_base;

    if (idx < N) {
        int off = base + incl - v;
        g_offs[idx] = off;
        g_cursor[idx] = off;
    }
    if (b == NB - 1 && tid == 0) g_offs[N] = base + agg;
}

// ---------------------------------------------------------------------------
// 4) Scatter src ids into dst-sorted order (cursor pre-seeded with offsets).
// ---------------------------------------------------------------------------
__global__ void scatter_kernel(const int* __restrict__ src,
                               const int* __restrict__ dst, int E) {
    int e = blockIdx.x * blockDim.x + threadIdx.x;
    if (e >= E) return;
    int pos = atomicAdd(&g_cursor[dst[e]], 1);
    g_srcs[pos] = src[e];
}

// ---------------------------------------------------------------------------
// 5) Per-node projections with packed fp32x2 FMA (Blackwell FFMA2):
//    h = x@Wl + bl (stored fp16), packed (u, as_h) and (v, ad_h) per head.
// ---------------------------------------------------------------------------
__global__ void __launch_bounds__(128)
node_kernel(const float* __restrict__ x,
            const float* __restrict__ Wl,
            const float* __restrict__ bl,
            const float* __restrict__ Wa,
            int N) {
    __shared__ __align__(16) float s_wl[DIN * FEAT];
    __shared__ __align__(16) float s_bl[FEAT];
    __shared__ float s_wa[2 * HDIM];
    __shared__ float s_cu[DIN], s_cv[DIN];

    for (int i = threadIdx.x; i < DIN * FEAT; i += blockDim.x) s_wl[i] = Wl[i];
    if (threadIdx.x < FEAT) {
        s_bl[threadIdx.x] = bl[threadIdx.x];
        s_cu[threadIdx.x] = g_P.cu[threadIdx.x];
        s_cv[threadIdx.x] = g_P.cv[threadIdx.x];
    }
    if (threadIdx.x < 2 * HDIM) s_wa[threadIdx.x] = Wa[threadIdx.x];
    __syncthreads();

    int n = blockIdx.x * blockDim.x + threadIdx.x;
    if (n >= N) return;

    unsigned long long acc2[FEAT / 2];
    const ulonglong2* blp = reinterpret_cast<const ulonglong2*>(s_bl);
#pragma unroll
    for (int q = 0; q < FEAT / 4; q++) {
        ulonglong2 b2 = blp[q];
        acc2[q * 2 + 0] = b2.x;
        acc2[q * 2 + 1] = b2.y;
    }
    float u = 0.f, v = 0.f;

    const float4* xr = reinterpret_cast<const float4*>(x + (size_t)n * DIN);
#pragma unroll 1
    for (int i4 = 0; i4 < DIN / 4; i4++) {
        float4 xv = xr[i4];
        float xs[4] = {xv.x, xv.y, xv.z, xv.w};
#pragma unroll
        for (int j = 0; j < 4; j++) {
            int i = i4 * 4 + j;
            float xi = xs[j];
            u += xi * s_cu[i];
            v += xi * s_cv[i];
            unsigned long long xi2;
            asm("mov.b64 %0, {%1, %1};" : "=l"(xi2) : "f"(xi));
            const ulonglong2* wrow =
                reinterpret_cast<const ulonglong2*>(&s_wl[i * FEAT]);
#pragma unroll
            for (int q = 0; q < FEAT / 4; q++) {
                ulonglong2 wv = wrow[q];
                asm("fma.rn.f32x2 %0, %1, %2, %0;"
                    : "+l"(acc2[q * 2 + 0]) : "l"(wv.x), "l"(xi2));
                asm("fma.rn.f32x2 %0, %1, %2, %0;"
                    : "+l"(acc2[q * 2 + 1]) : "l"(wv.y), "l"(xi2));
            }
        }
    }

    float accf[FEAT];
#pragma unroll
    for (int k = 0; k < FEAT / 2; k++)
        asm("mov.b64 {%0, %1}, %2;"
            : "=f"(accf[2 * k]), "=f"(accf[2 * k + 1]) : "l"(acc2[k]));

    __half2* hout = reinterpret_cast<__half2*>(&g_h[(size_t)n * FEAT]);
#pragma unroll
    for (int o2 = 0; o2 < FEAT / 2; o2++)
        hout[o2] = __floats2half2_rn(accf[o2 * 2 + 0], accf[o2 * 2 + 1]);

#pragma unroll
    for (int h = 0; h < NHEAD; h++) {
        float as = 0.f, ad = 0.f;
#pragma unroll
        for (int k = 0; k < HDIM; k++) {
            float hv = accf[h * HDIM + k];
            as += hv * s_wa[k];
            ad += hv * s_wa[HDIM + k];
        }
        g_uas[n * NHEAD + h] = make_float2(u, as);
        g_vad[n * NHEAD + h] = make_float2(v, ad);
    }
}

// ---------------------------------------------------------------------------
// 6) CSR reduce: 8 threads per dst node. Lane t handles 8 fp16 features
//    (one 16 B uint4 of the h row); head = t>>1. A warp serves 4 nodes.
//    Per edge: 1 h-LDG + 1 packed (u,as) LDG + broadcast src index; scalar
//    sign/exp chain runs on 8 lanes (was 16). fp32 accumulation, no atomics.
// ---------------------------------------------------------------------------
__global__ void __launch_bounds__(256)
reduce_kernel(float* __restrict__ out, int N) {
    int gid = blockIdx.x * blockDim.x + threadIdx.x;
    int n = gid >> 3;
    if (n >= N) return;
    int t = gid & 7;
    int head = t >> 1;

    int beg = g_offs[n];
    int end = g_offs[n + 1];

    float2 vad = __ldg(&g_vad[n * NHEAD + head]);
    float vofs = vad.x + g_P.off;     // folded per-node sign offset
    float adb  = vad.y + g_P.ba;

    float acc[8] = {0.f, 0.f, 0.f, 0.f, 0.f, 0.f, 0.f, 0.f};
    float dsum = 0.f;

    if (beg < end) {
        int s = __ldg(&g_srcs[beg]);
        for (int p = beg; p < end; p++) {
            int s_next = (p + 1 < end) ? __ldg(&g_srcs[p + 1]) : 0;
            float2 ua = __ldg(&g_uas[s * NHEAD + head]);
            // 8 fp16 features = 16 bytes, one uint4 load
            uint4 raw = *reinterpret_cast<const uint4*>(&g_h[(size_t)s * FEAT + t * 8]);
            float2 h01 = __half22float2(*reinterpret_cast<const __half2*>(&raw.x));
            float2 h23 = __half22float2(*reinterpret_cast<const __half2*>(&raw.y));
            float2 h45 = __half22float2(*reinterpret_cast<const __half2*>(&raw.z));
            float2 h67 = __half22float2(*reinterpret_cast<const __half2*>(&raw.w));

            float arg = ua.x + vofs;
            float sg = (arg > 0.f) ? 1.f : ((arg < 0.f) ? -1.f : 0.f);
            float al = sg * ua.y + adb;
            al = (al > 0.f) ? al : 0.01f * al;          // leaky_relu
            float w = __expf(al);
            float ws = w * sg;
            acc[0] += ws * h01.x;  acc[1] += ws * h01.y;
            acc[2] += ws * h23.x;  acc[3] += ws * h23.y;
            acc[4] += ws * h45.x;  acc[5] += ws * h45.y;
            acc[6] += ws * h67.x;  acc[7] += ws * h67.y;
            dsum += w;
            s = s_next;
        }
    }

    float inv = 1.f / fmaxf(dsum, 1e-16f);
    float* op = &out[(size_t)n * FEAT + t * 8];
    *reinterpret_cast<float4*>(op) =
        make_float4(acc[0] * inv, acc[1] * inv, acc[2] * inv, acc[3] * inv);
    *reinterpret_cast<float4*>(op + 4) =
        make_float4(acc[4] * inv, acc[5] * inv, acc[6] * inv, acc[7] * inv);
}

// ---------------------------------------------------------------------------
extern "C" void kernel_launch(void* const* d_in, const int* in_sizes, int n_in,
                              void* d_out, int out_size) {
    const float* x   = (const float*)d_in[0];
    const int*   src = (const int*)  d_in[1];
    const int*   dst = (const int*)  d_in[2];
    const float* Wl  = (const float*)d_in[3];
    const float* bl  = (const float*)d_in[4];
    const float* Wa  = (const float*)d_in[5];
    const float* ba  = (const float*)d_in[6];
    const float* Wd  = (const float*)d_in[7];
    const float* bd  = (const float*)d_in[8];
    const float* Wf  = (const float*)d_in[9];
    const float* bf  = (const float*)d_in[10];
    float* out = (float*)d_out;

    int N = in_sizes[0] / DIN;
    int E = in_sizes[1];
    int NB = (N + SCAN_B - 1) / SCAN_B;

    // One-time stream/event setup (host resources, not device memory).
    static cudaStream_t s_side = nullptr;
    static cudaEvent_t  ev_fork = nullptr, ev_join = nullptr;
    static int* p_degfv = nullptr;
    if (s_side == nullptr) {
        cudaStreamCreateWithFlags(&s_side, cudaStreamNonBlocking);
        cudaEventCreateWithFlags(&ev_fork, cudaEventDisableTiming);
        cudaEventCreateWithFlags(&ev_join, cudaEventDisableTiming);
        cudaGetSymbolAddress((void**)&p_degfv, g_degfv);
    }

    // Fork: side stream builds the CSR while the main stream runs the
    // dense projections.
    cudaEventRecord(ev_fork, 0);
    cudaStreamWaitEvent(s_side, ev_fork, 0);

    cudaMemsetAsync(p_degfv, 0, (size_t)(N + NB) * sizeof(int), s_side);
    hist_kernel<<<(E + 255) / 256, 256, 0, s_side>>>(dst, E);
    scan_onepass_kernel<<<NB, SCAN_B, 0, s_side>>>(N, NB);
    scatter_kernel<<<(E + 255) / 256, 256, 0, s_side>>>(src, dst, E);
    cudaEventRecord(ev_join, s_side);

    precompute_kernel<<<1, 64>>>(Wd, bd, Wf, bf, ba);
    node_kernel<<<(N + 127) / 128, 128>>>(x, Wl, bl, Wa, N);

    // Join, then reduce (8 threads per node).
    cudaStreamWaitEvent(0, ev_join, 0);
    long long threads = (long long)N * 8;
    int blocks = (int)((threads + 255) / 256);
    reduce_kernel<<<blocks, 256>>>(out, N);
}

// round 12
// speedup vs baseline: 1.3183x; 1.0246x over previous
#include <cuda_runtime.h>
#include <cuda_fp16.h>

#define NMAX   100000
#define EMAX   1600000
#define DIN    64
#define NHEAD  4
#define HDIM   16
#define FEAT   64   // NHEAD*HDIM
#define SCAN_B 1024
#define NBMAX  256

// -------- scratch (static device globals; no allocations allowed) ----------
__device__ __align__(16) static __half g_h[(size_t)NMAX * FEAT];  // fp16 node features
__device__ __align__(16) static float2 g_uas[NMAX * NHEAD];  // (u, as_head) packed
__device__ __align__(16) static float2 g_vad[NMAX * NHEAD];  // (v, ad_head) packed

// deg + publish-flags share one memset region: [0,NMAX) = deg, [NMAX,NMAX+NBMAX) = flags
__device__ static int g_degfv[NMAX + NBMAX];
__device__ static int g_cursor[NMAX];      // seeded with offs; scatter bumps it
__device__ static int g_offs[NMAX + 1];
__device__ static int g_srcs[EMAX];        // src node id per edge, sorted by dst

struct Params {
    float cu[DIN];   // Wd @ (Wf[0:64]  + Wf[128:192])
    float cv[DIN];   // Wd @ (Wf[64:128] - Wf[128:192])
    float off;       // bd . (wfu + wfv) + bf
    float ba;        // attention bias scalar
};
__device__ static Params g_P;

// ---------------------------------------------------------------------------
// 1) Fold the rank-1 edge linears into per-node projection vectors.
//    512 threads: row r = tid/8, 8-way K-split + shfl reduction.
// ---------------------------------------------------------------------------
__global__ void __launch_bounds__(512)
precompute_kernel(const float* __restrict__ Wd,
                  const float* __restrict__ bd,
                  const float* __restrict__ Wf,
                  const float* __restrict__ bf,
                  const float* __restrict__ ba) {
    __shared__ float wfu[DIN], wfv[DIN], red[DIN];
    int tid = threadIdx.x;   // 512
    if (tid < DIN) {
        float f0 = Wf[tid], f1 = Wf[DIN + tid], f2 = Wf[2 * DIN + tid];
        wfu[tid] = f0 + f2;
        wfv[tid] = f1 - f2;
        red[tid] = bd[tid] * (wfu[tid] + wfv[tid]);
    }
    __syncthreads();

    int r = tid >> 3;        // row 0..63
    int part = tid & 7;      // K-chunk 0..7
    float cu = 0.f, cv = 0.f;
#pragma unroll
    for (int jj = 0; jj < 8; jj++) {
        int j = part * 8 + jj;
        float w = Wd[r * DIN + j];
        cu += w * wfu[j];
        cv += w * wfv[j];
    }
#pragma unroll
    for (int o = 4; o > 0; o >>= 1) {
        cu += __shfl_down_sync(0xffffffffu, cu, o);
        cv += __shfl_down_sync(0xffffffffu, cv, o);
    }
    if (part == 0) {
        g_P.cu[r] = cu;
        g_P.cv[r] = cv;
    }
    if (tid == 0) {
        float s = bf[0];
        for (int j = 0; j < DIN; j++) s += red[j];
        g_P.off = s;
        g_P.ba  = ba[0];
    }
}

// ---------------------------------------------------------------------------
// 2) Degree histogram over dst (deg zeroed by cudaMemsetAsync).
// ---------------------------------------------------------------------------
__global__ void hist_kernel(const int* __restrict__ dst, int E) {
    int e = blockIdx.x * blockDim.x + threadIdx.x;
    if (e < E) atomicAdd(&g_degfv[dst[e]], 1);
}

// ---------------------------------------------------------------------------
// 3) Single-pass exclusive scan (98 co-resident blocks, aggregate lookback).
// ---------------------------------------------------------------------------
__global__ void scan_onepass_kernel(int N, int NB) {
    __shared__ int sm[SCAN_B];
    __shared__ int s_base;
    int b = blockIdx.x;
    int tid = threadIdx.x;
    int idx = b * SCAN_B + tid;

    int v = (idx < N) ? g_degfv[idx] : 0;
    sm[tid] = v;
    __syncthreads();
#pragma unroll
    for (int o = 1; o < SCAN_B; o <<= 1) {
        int tmp = (tid >= o) ? sm[tid - o] : 0;
        __syncthreads();
        sm[tid] += tmp;
        __syncthreads();
    }
    int incl = sm[tid];
    int agg = sm[SCAN_B - 1];

    if (tid == 0) {
        __threadfence();
        atomicExch(&g_degfv[NMAX + b], agg + 1);
    }

    if (tid < 32) {
        int contrib = 0;
        for (int t = tid; t < b; t += 32) {
            int fv;
            do { fv = atomicAdd(&g_degfv[NMAX + t], 0); } while (fv == 0);
            contrib += fv - 1;
        }
#pragma unroll
        for (int o = 16; o > 0; o >>= 1)
            contrib += __shfl_down_sync(0xffffffffu, contrib, o);
        if (tid == 0) s_base = contrib;
    }
    __syncthreads();
    int base = s_base;

    if (idx < N) {
        int off = base + incl - v;
        g_offs[idx] = off;
        g_cursor[idx] = off;
    }
    if (b == NB - 1 && tid == 0) g_offs[N] = base + agg;
}

// ---------------------------------------------------------------------------
// 4) Scatter src ids into dst-sorted order (cursor pre-seeded with offsets).
// ---------------------------------------------------------------------------
__global__ void scatter_kernel(const int* __restrict__ src,
                               const int* __restrict__ dst, int E) {
    int e = blockIdx.x * blockDim.x + threadIdx.x;
    if (e >= E) return;
    int pos = atomicAdd(&g_cursor[dst[e]], 1);
    g_srcs[pos] = src[e];
}

// ---------------------------------------------------------------------------
// 5) Per-node projections with packed fp32x2 FMA (Blackwell FFMA2):
//    h = x@Wl + bl (stored fp16), packed (u, as_h) and (v, ad_h) per head.
// ---------------------------------------------------------------------------
__global__ void __launch_bounds__(128)
node_kernel(const float* __restrict__ x,
            const float* __restrict__ Wl,
            const float* __restrict__ bl,
            const float* __restrict__ Wa,
            int N) {
    __shared__ __align__(16) float s_wl[DIN * FEAT];
    __shared__ __align__(16) float s_bl[FEAT];
    __shared__ float s_wa[2 * HDIM];
    __shared__ float s_cu[DIN], s_cv[DIN];

    for (int i = threadIdx.x; i < DIN * FEAT; i += blockDim.x) s_wl[i] = Wl[i];
    if (threadIdx.x < FEAT) {
        s_bl[threadIdx.x] = bl[threadIdx.x];
        s_cu[threadIdx.x] = g_P.cu[threadIdx.x];
        s_cv[threadIdx.x] = g_P.cv[threadIdx.x];
    }
    if (threadIdx.x < 2 * HDIM) s_wa[threadIdx.x] = Wa[threadIdx.x];
    __syncthreads();

    int n = blockIdx.x * blockDim.x + threadIdx.x;
    if (n >= N) return;

    unsigned long long acc2[FEAT / 2];
    const ulonglong2* blp = reinterpret_cast<const ulonglong2*>(s_bl);
#pragma unroll
    for (int q = 0; q < FEAT / 4; q++) {
        ulonglong2 b2 = blp[q];
        acc2[q * 2 + 0] = b2.x;
        acc2[q * 2 + 1] = b2.y;
    }
    float u = 0.f, v = 0.f;

    const float4* xr = reinterpret_cast<const float4*>(x + (size_t)n * DIN);
#pragma unroll 1
    for (int i4 = 0; i4 < DIN / 4; i4++) {
        float4 xv = xr[i4];
        float xs[4] = {xv.x, xv.y, xv.z, xv.w};
#pragma unroll
        for (int j = 0; j < 4; j++) {
            int i = i4 * 4 + j;
            float xi = xs[j];
            u += xi * s_cu[i];
            v += xi * s_cv[i];
            unsigned long long xi2;
            asm("mov.b64 %0, {%1, %1};" : "=l"(xi2) : "f"(xi));
            const ulonglong2* wrow =
                reinterpret_cast<const ulonglong2*>(&s_wl[i * FEAT]);
#pragma unroll
            for (int q = 0; q < FEAT / 4; q++) {
                ulonglong2 wv = wrow[q];
                asm("fma.rn.f32x2 %0, %1, %2, %0;"
                    : "+l"(acc2[q * 2 + 0]) : "l"(wv.x), "l"(xi2));
                asm("fma.rn.f32x2 %0, %1, %2, %0;"
                    : "+l"(acc2[q * 2 + 1]) : "l"(wv.y), "l"(xi2));
            }
        }
    }

    float accf[FEAT];
#pragma unroll
    for (int k = 0; k < FEAT / 2; k++)
        asm("mov.b64 {%0, %1}, %2;"
            : "=f"(accf[2 * k]), "=f"(accf[2 * k + 1]) : "l"(acc2[k]));

    __half2* hout = reinterpret_cast<__half2*>(&g_h[(size_t)n * FEAT]);
#pragma unroll
    for (int o2 = 0; o2 < FEAT / 2; o2++)
        hout[o2] = __floats2half2_rn(accf[o2 * 2 + 0], accf[o2 * 2 + 1]);

#pragma unroll
    for (int h = 0; h < NHEAD; h++) {
        float as = 0.f, ad = 0.f;
#pragma unroll
        for (int k = 0; k < HDIM; k++) {
            float hv = accf[h * HDIM + k];
            as += hv * s_wa[k];
            ad += hv * s_wa[HDIM + k];
        }
        g_uas[n * NHEAD + h] = make_float2(u, as);
        g_vad[n * NHEAD + h] = make_float2(v, ad);
    }
}

// ---------------------------------------------------------------------------
// 6) CSR reduce: 4 threads per dst node. Lane t == head t, handling that
//    head's 16 fp16 features (two independent uint4 loads). A warp serves
//    8 nodes/edges per iteration. fp32 accumulation, no atomics.
// ---------------------------------------------------------------------------
__global__ void __launch_bounds__(256)
reduce_kernel(float* __restrict__ out, int N) {
    int gid = blockIdx.x * blockDim.x + threadIdx.x;
    int n = gid >> 2;
    if (n >= N) return;
    int head = gid & 3;

    int beg = g_offs[n];
    int end = g_offs[n + 1];

    float2 vad = __ldg(&g_vad[n * NHEAD + head]);
    float vofs = vad.x + g_P.off;     // folded per-node sign offset
    float adb  = vad.y + g_P.ba;

    float acc[16];
#pragma unroll
    for (int k = 0; k < 16; k++) acc[k] = 0.f;
    float dsum = 0.f;

    if (beg < end) {
        int s = __ldg(&g_srcs[beg]);
        for (int p = beg; p < end; p++) {
            int s_next = (p + 1 < end) ? __ldg(&g_srcs[p + 1]) : 0;
            float2 ua = __ldg(&g_uas[s * NHEAD + head]);
            // 16 fp16 features = 32 bytes, two independent uint4 loads
            const uint4* hp = reinterpret_cast<const uint4*>(
                &g_h[(size_t)s * FEAT + head * HDIM]);
            uint4 raw0 = hp[0];
            uint4 raw1 = hp[1];

            float arg = ua.x + vofs;
            float sg = (arg > 0.f) ? 1.f : ((arg < 0.f) ? -1.f : 0.f);
            float al = sg * ua.y + adb;
            al = (al > 0.f) ? al : 0.01f * al;          // leaky_relu
            float w = __expf(al);
            float ws = w * sg;

            const __half2* c0 = reinterpret_cast<const __half2*>(&raw0);
            const __half2* c1 = reinterpret_cast<const __half2*>(&raw1);
#pragma unroll
            for (int q = 0; q < 4; q++) {
                float2 f0 = __half22float2(c0[q]);
                float2 f1 = __half22float2(c1[q]);
                acc[q * 2 + 0] += ws * f0.x;
                acc[q * 2 + 1] += ws * f0.y;
                acc[8 + q * 2 + 0] += ws * f1.x;
                acc[8 + q * 2 + 1] += ws * f1.y;
            }
            dsum += w;
            s = s_next;
        }
    }

    float inv = 1.f / fmaxf(dsum, 1e-16f);
    float* op = &out[(size_t)n * FEAT + head * HDIM];
#pragma unroll
    for (int q = 0; q < 4; q++)
        reinterpret_cast<float4*>(op)[q] =
            make_float4(acc[q * 4 + 0] * inv, acc[q * 4 + 1] * inv,
                        acc[q * 4 + 2] * inv, acc[q * 4 + 3] * inv);
}

// ---------------------------------------------------------------------------
extern "C" void kernel_launch(void* const* d_in, const int* in_sizes, int n_in,
                              void* d_out, int out_size) {
    const float* x   = (const float*)d_in[0];
    const int*   src = (const int*)  d_in[1];
    const int*   dst = (const int*)  d_in[2];
    const float* Wl  = (const float*)d_in[3];
    const float* bl  = (const float*)d_in[4];
    const float* Wa  = (const float*)d_in[5];
    const float* ba  = (const float*)d_in[6];
    const float* Wd  = (const float*)d_in[7];
    const float* bd  = (const float*)d_in[8];
    const float* Wf  = (const float*)d_in[9];
    const float* bf  = (const float*)d_in[10];
    float* out = (float*)d_out;

    int N = in_sizes[0] / DIN;
    int E = in_sizes[1];
    int NB = (N + SCAN_B - 1) / SCAN_B;

    // One-time stream/event setup (host resources, not device memory).
    static cudaStream_t s_side = nullptr;
    static cudaEvent_t  ev_fork = nullptr, ev_join = nullptr;
    static int* p_degfv = nullptr;
    if (s_side == nullptr) {
        cudaStreamCreateWithFlags(&s_side, cudaStreamNonBlocking);
        cudaEventCreateWithFlags(&ev_fork, cudaEventDisableTiming);
        cudaEventCreateWithFlags(&ev_join, cudaEventDisableTiming);
        cudaGetSymbolAddress((void**)&p_degfv, g_degfv);
    }

    // Fork: side stream builds the CSR while the main stream runs the
    // dense projections.
    cudaEventRecord(ev_fork, 0);
    cudaStreamWaitEvent(s_side, ev_fork, 0);

    cudaMemsetAsync(p_degfv, 0, (size_t)(N + NB) * sizeof(int), s_side);
    hist_kernel<<<(E + 255) / 256, 256, 0, s_side>>>(dst, E);
    scan_onepass_kernel<<<NB, SCAN_B, 0, s_side>>>(N, NB);
    scatter_kernel<<<(E + 255) / 256, 256, 0, s_side>>>(src, dst, E);
    cudaEventRecord(ev_join, s_side);

    precompute_kernel<<<1, 512>>>(Wd, bd, Wf, bf, ba);
    node_kernel<<<(N + 127) / 128, 128>>>(x, Wl, bl, Wa, N);

    // Join, then reduce (4 threads per node).
    cudaStreamWaitEvent(0, ev_join, 0);
    long long threads = (long long)N * 4;
    int blocks = (int)((threads + 255) / 256);
    reduce_kernel<<<blocks, 256>>>(out, N);
}